// round 12
// baseline (speedup 1.0000x reference)
#include <cuda_runtime.h>
#include <cuda_bf16.h>
#include <math.h>
#include <stdint.h>

// Problem constants
#define BB   2
#define HH   16
#define SS   2048
#define DDIM 1024
#define DH   64
#define PFX  32
#define LKV  2080          // PFX + SS = 65 * 32
#define BIAS_STRIDE 4160
#define BIAS_OFF 2079

// ---------------- scratch (static device globals; no allocation) ----------------
__device__ float g_bias[HH * BIAS_STRIDE];                   // [h][rel+2079]
__device__ __nv_bfloat16 g_ah[(size_t)BB * SS * DDIM];       // hidden hi [m][k]
__device__ __nv_bfloat16 g_al[(size_t)BB * SS * DDIM];       // hidden lo
__device__ __nv_bfloat16 g_wh[(size_t)4 * DDIM * DDIM];      // W hi, transposed [n][k]
__device__ __nv_bfloat16 g_wl[(size_t)4 * DDIM * DDIM];      // W lo
__device__ __nv_bfloat16 g_oh[(size_t)BB * SS * DDIM];       // attn-out hi
__device__ __nv_bfloat16 g_ol[(size_t)BB * SS * DDIM];       // attn-out lo
__device__ __nv_bfloat16 g_qh[(size_t)BB * HH * SS * DH];    // [bh][s][d]
__device__ __nv_bfloat16 g_ql[(size_t)BB * HH * SS * DH];
__device__ __nv_bfloat16 g_kh[(size_t)BB * HH * LKV * DH];   // [bh][key][d]
__device__ __nv_bfloat16 g_kl[(size_t)BB * HH * LKV * DH];
__device__ __nv_bfloat16 g_vh[(size_t)BB * HH * LKV * DH];
__device__ __nv_bfloat16 g_vl[(size_t)BB * HH * LKV * DH];

// ======================= PTX helpers (sm_80-class only) =======================
__device__ __forceinline__ uint32_t smem_u32(const void* p) {
    uint32_t a;
    asm("{ .reg .u64 t; cvta.to.shared.u64 t, %1; cvt.u32.u64 %0, t; }" : "=r"(a) : "l"(p));
    return a;
}
__device__ __forceinline__ void cpa16(uint32_t dst, const void* src) {
    asm volatile("cp.async.cg.shared.global [%0], [%1], 16;" :: "r"(dst), "l"(src));
}
__device__ __forceinline__ void ldsm_x4(uint32_t* r, uint32_t addr) {
    asm volatile("ldmatrix.sync.aligned.m8n8.x4.shared.b16 {%0,%1,%2,%3}, [%4];"
                 : "=r"(r[0]), "=r"(r[1]), "=r"(r[2]), "=r"(r[3]) : "r"(addr));
}
__device__ __forceinline__ void ldsm_x4_t(uint32_t* r, uint32_t addr) {
    asm volatile("ldmatrix.sync.aligned.m8n8.x4.trans.shared.b16 {%0,%1,%2,%3}, [%4];"
                 : "=r"(r[0]), "=r"(r[1]), "=r"(r[2]), "=r"(r[3]) : "r"(addr));
}
__device__ __forceinline__ void mma16816(float* d, const uint32_t* a, const uint32_t* b) {
    asm volatile("mma.sync.aligned.m16n8k16.row.col.f32.bf16.bf16.f32 "
                 "{%0,%1,%2,%3}, {%4,%5,%6,%7}, {%8,%9}, {%0,%1,%2,%3};"
                 : "+f"(d[0]), "+f"(d[1]), "+f"(d[2]), "+f"(d[3])
                 : "r"(a[0]), "r"(a[1]), "r"(a[2]), "r"(a[3]), "r"(b[0]), "r"(b[1]));
}
__device__ __forceinline__ uint32_t pkb2(__nv_bfloat16 a, __nv_bfloat16 b) {
    uint16_t ua = *(uint16_t*)&a, ub = *(uint16_t*)&b;
    return (uint32_t)ua | ((uint32_t)ub << 16);
}
// 128B-row swizzled smem element address (same pattern as attention tiles)
__device__ __forceinline__ uint32_t sw_addr128(uint32_t base, int r, int k) {
    int quad = k >> 3;                 // 0..7
    int sw   = quad ^ (r & 7);
    return base + r * 128 + sw * 16 + (k & 7) * 2;
}
#define CP_COMMIT() asm volatile("cp.async.commit_group;" ::: "memory")

// ---------------- fused preprocessing kernel ----------------
#define PREP_BLOCKS 8706

__global__ __launch_bounds__(256) void prep_kernel(
        const float* __restrict__ hidden,
        const float* __restrict__ Wq, const float* __restrict__ Wk,
        const float* __restrict__ Wv, const float* __restrict__ Wo,
        const float* __restrict__ pk, const float* __restrict__ pv,
        const float* __restrict__ rel_table)
{
    __shared__ float tile[32][33];
    const int bid = blockIdx.x;
    const int tid = threadIdx.x;

    if (bid < 4096) {
        int i4 = bid * 256 + tid;
        float4 x = *(const float4*)(hidden + (size_t)i4 * 4);
        __nv_bfloat16 h0 = __float2bfloat16(x.x), h1 = __float2bfloat16(x.y);
        __nv_bfloat16 h2 = __float2bfloat16(x.z), h3 = __float2bfloat16(x.w);
        uint32_t hiA = pkb2(h0, h1), hiB = pkb2(h2, h3);
        uint32_t loA = pkb2(__float2bfloat16(x.x - __bfloat162float(h0)),
                            __float2bfloat16(x.y - __bfloat162float(h1)));
        uint32_t loB = pkb2(__float2bfloat16(x.z - __bfloat162float(h2)),
                            __float2bfloat16(x.w - __bfloat162float(h3)));
        size_t b = (size_t)i4 * 4;
        uint32_t* ph = (uint32_t*)(g_ah + b);
        ph[0] = hiA; ph[1] = hiB;
        uint32_t* pl = (uint32_t*)(g_al + b);
        pl[0] = loA; pl[1] = loB;
    } else if (bid < 8192) {
        int zz = bid - 4096;
        int z  = zz >> 10;
        int zb = zz & 1023;
        int n0 = (zb & 31) * 32, k0 = (zb >> 5) * 32;
        const float* W = (z == 0) ? Wq : (z == 1) ? Wk : (z == 2) ? Wv : Wo;
        __nv_bfloat16* dh = g_wh + (size_t)z * DDIM * DDIM;
        __nv_bfloat16* dl = g_wl + (size_t)z * DDIM * DDIM;
        const int tx = tid & 31, ty0 = tid >> 5;
        #pragma unroll
        for (int r = 0; r < 4; r++) {
            int ty = ty0 + r * 8;
            tile[ty][tx] = W[(size_t)(k0 + ty) * DDIM + n0 + tx];
        }
        __syncthreads();
        #pragma unroll
        for (int r = 0; r < 4; r++) {
            int ty = ty0 + r * 8;
            float x = tile[tx][ty];
            __nv_bfloat16 h = __float2bfloat16(x);
            __nv_bfloat16 l = __float2bfloat16(x - __bfloat162float(h));
            size_t b = (size_t)(n0 + ty) * DDIM + (k0 + tx);
            dh[b] = h;
            dl[b] = l;
        }
    } else if (bid < 8450) {
        int idx = (bid - 8192) * 256 + tid;
        if (idx < HH * 4127) {
            int h   = idx / 4127;
            int r   = idx - h * 4127;
            int rel = r - BIAS_OFF;
            int ret = (rel > 0) ? 16 : 0;
            int n   = rel < 0 ? -rel : rel;
            int bkt;
            if (n < 8) {
                bkt = n;
            } else {
                float nf = (float)n;
                int vl = 8 + (int)(logf(nf * 0.125f) / 2.772588722239781f * 8.0f);
                bkt = vl < 15 ? vl : 15;
            }
            bkt += ret;
            g_bias[h * BIAS_STRIDE + r] = rel_table[bkt * HH + h];
        }
    } else {
        int idx = (bid - 8450) * 256 + tid;
        int d  = idx & 63;
        int p  = (idx >> 6) & 31;
        int bh = idx >> 11;
        size_t o = ((size_t)bh * LKV + p) * DH + d;
        float kx = pk[idx], vx = pv[idx];
        __nv_bfloat16 khf = __float2bfloat16(kx);
        __nv_bfloat16 vhf = __float2bfloat16(vx);
        g_kh[o] = khf;
        g_kl[o] = __float2bfloat16(kx - __bfloat162float(khf));
        g_vh[o] = vhf;
        g_vl[o] = __float2bfloat16(vx - __bfloat162float(vhf));
    }
}

// ---------------- mma.sync bf16 GEMM: C = [Ahi|Ahi|Alo] * [Whi|Wlo|Whi]^T ----------------
// CHUNK=64 k-elems (128B rows), NSTG=3 (96KB dyn smem), NCH=48:
//   chunks 0-15:  Ah x Wh;  16-31: Ah x Wl;  32-47: Al x Wh;  off (c&15)*64.
// One barrier per chunk (48 total), 4 unrolled k-steps per window.
#define CHUNK 64
#define NSTG 3
#define STG_BYTES 32768          // A 16KB + B 16KB
#define NCH 48
#define GEMM_SMEM (NSTG * STG_BYTES)

__device__ __forceinline__ void gemm_load_chunk(uint32_t sb,
        const __nv_bfloat16* __restrict__ Ah, const __nv_bfloat16* __restrict__ Al,
        const __nv_bfloat16* __restrict__ Wh, const __nv_bfloat16* __restrict__ Wl,
        int mblock, int nblock, int c)
{
    const int t = threadIdx.x;
    const int st = c % NSTG;
    uint32_t ab = sb + st * STG_BYTES;
    uint32_t bb = ab + 16384;
    const __nv_bfloat16* Ag = (c < 32) ? Ah : Al;
    const __nv_bfloat16* Wg = (c < 16 || c >= 32) ? Wh : Wl;
    const int co = (c & 15) * CHUNK;
    #pragma unroll
    for (int i = 0; i < 4; i++) {
        int idx = t + i * 256;               // 0..1023: 128 rows x 8 quads
        int r = idx >> 3, q = idx & 7;
        uint32_t soff = (uint32_t)(r * 128 + ((q ^ (r & 7)) << 4));
        const char* as = (const char*)(Ag + (size_t)(mblock + r) * DDIM + co + q * 8);
        const char* bs = (const char*)(Wg + (size_t)(nblock + r) * DDIM + co + q * 8);
        cpa16(ab + soff, as);
        cpa16(bb + soff, bs);
    }
    CP_COMMIT();
}

__device__ __forceinline__ void gemm_mma_body(
        const __nv_bfloat16* __restrict__ Ah, const __nv_bfloat16* __restrict__ Al,
        const __nv_bfloat16* __restrict__ Wh, const __nv_bfloat16* __restrict__ Wl,
        int mblock, int nblock, int flavor, float* __restrict__ outp)
{
    extern __shared__ __align__(128) char smbuf[];
    uint32_t sb = smem_u32(smbuf);
    const int t    = threadIdx.x;
    const int lane = t & 31;
    const int w    = t >> 5;
    const int wm   = w >> 1;
    const int wn   = w & 1;

    float acc[2][8][4];
    #pragma unroll
    for (int f = 0; f < 2; f++)
        #pragma unroll
        for (int p = 0; p < 8; p++)
            #pragma unroll
            for (int e = 0; e < 4; e++) acc[f][p][e] = 0.f;

    gemm_load_chunk(sb, Ah, Al, Wh, Wl, mblock, nblock, 0);
    gemm_load_chunk(sb, Ah, Al, Wh, Wl, mblock, nblock, 1);

    for (int c = 0; c < NCH; c++) {
        if (c < NCH - 1) asm volatile("cp.async.wait_group 1;" ::: "memory");
        else             asm volatile("cp.async.wait_group 0;" ::: "memory");
        __syncthreads();
        // stage (c+2)%3 == (c-1)%3: its readers finished at iter c-1 (barrier above)
        if (c + 2 < NCH) gemm_load_chunk(sb, Ah, Al, Wh, Wl, mblock, nblock, c + 2);

        uint32_t ab = sb + (c % NSTG) * STG_BYTES;
        uint32_t bb = ab + 16384;

        #pragma unroll
        for (int ks = 0; ks < 4; ks++) {
            uint32_t afr[2][4];
            #pragma unroll
            for (int f = 0; f < 2; f++) {
                int r = wm * 32 + f * 16 + (lane & 15);
                int k = ks * 16 + (lane >> 4) * 8;
                ldsm_x4(afr[f], sw_addr128(ab, r, k));
            }
            uint32_t bfr[8][2];
            #pragma unroll
            for (int p = 0; p < 4; p++) {
                int n = wn * 64 + p * 16 + ((lane >> 4) & 1) * 8 + (lane & 7);
                int k = ks * 16 + ((lane >> 3) & 1) * 8;
                uint32_t r4[4];
                ldsm_x4(r4, sw_addr128(bb, n, k));
                bfr[p * 2][0]     = r4[0];
                bfr[p * 2][1]     = r4[1];
                bfr[p * 2 + 1][0] = r4[2];
                bfr[p * 2 + 1][1] = r4[3];
            }
            #pragma unroll
            for (int f = 0; f < 2; f++)
                #pragma unroll
                for (int p = 0; p < 8; p++)
                    mma16816(acc[f][p], afr[f], bfr[p]);
        }
    }

    #pragma unroll
    for (int f = 0; f < 2; f++) {
        #pragma unroll
        for (int p = 0; p < 8; p++) {
            #pragma unroll
            for (int e2 = 0; e2 < 2; e2++) {
                int m  = mblock + wm * 32 + f * 16 + (lane >> 2) + e2 * 8;
                int n0 = nblock + wn * 64 + p * 8 + ((lane & 3) << 1);
                float v0 = acc[f][p][e2 * 2], v1 = acc[f][p][e2 * 2 + 1];
                if (flavor == 3) {
                    outp[(size_t)m * DDIM + n0]     = v0;
                    outp[(size_t)m * DDIM + n0 + 1] = v1;
                } else {
                    __nv_bfloat16 h0 = __float2bfloat16(v0), h1 = __float2bfloat16(v1);
                    uint32_t hi = pkb2(h0, h1);
                    uint32_t lo = pkb2(__float2bfloat16(v0 - __bfloat162float(h0)),
                                       __float2bfloat16(v1 - __bfloat162float(h1)));
                    int b0 = m >> 11, s = m & 2047, hh = n0 >> 6, d = n0 & 63;
                    int bh = b0 * HH + hh;
                    if (flavor == 0) {
                        size_t o = ((size_t)bh * SS + s) * DH + d;
                        *(uint32_t*)(g_qh + o) = hi;
                        *(uint32_t*)(g_ql + o) = lo;
                    } else {
                        size_t o = ((size_t)bh * LKV + PFX + s) * DH + d;
                        if (flavor == 1) {
                            *(uint32_t*)(g_kh + o) = hi;
                            *(uint32_t*)(g_kl + o) = lo;
                        } else {
                            *(uint32_t*)(g_vh + o) = hi;
                            *(uint32_t*)(g_vl + o) = lo;
                        }
                    }
                }
            }
        }
    }
}

__global__ __launch_bounds__(256, 2) void gemm_qkv_mma()
{
    const int z = blockIdx.z;
    gemm_mma_body(g_ah, g_al,
                  g_wh + (size_t)z * DDIM * DDIM, g_wl + (size_t)z * DDIM * DDIM,
                  blockIdx.y * 128, blockIdx.x * 128, z, nullptr);
}

__global__ __launch_bounds__(256, 2) void gemm_o_mma(float* __restrict__ out)
{
    gemm_mma_body(g_oh, g_ol,
                  g_wh + (size_t)3 * DDIM * DDIM, g_wl + (size_t)3 * DDIM * DDIM,
                  blockIdx.y * 128, blockIdx.x * 128, 3, out);
}

// ---------------- mma.sync flash attention (paired 64-key softmax) ----------------
#define ATTN_SMEM 65536

__device__ __forceinline__ void attn_load_kv_nc(int t, int bh, int kt, uint32_t base)
{
    #pragma unroll
    for (int i = 0; i < 2; i++) {
        const int row = (t >> 3) + i * 16;
        const int c = t & 7;
        uint32_t off = (uint32_t)(row * 128 + ((c ^ (row & 7)) << 4));
        size_t goff = ((size_t)bh * LKV + kt * 32 + row) * DH + c * 8;
        cpa16(base + off,         g_kh + goff);
        cpa16(base + 4096 + off,  g_kl + goff);
        cpa16(base + 8192 + off,  g_vh + goff);
        cpa16(base + 12288 + off, g_vl + goff);
    }
}

__device__ __forceinline__ void qk32(float (*sfr)[4], uint32_t kbb,
        const uint32_t (*qh)[4], const uint32_t (*ql)[4], int lane)
{
    #pragma unroll
    for (int j = 0; j < 4; j++) {
        #pragma unroll
        for (int gk2 = 0; gk2 < 2; gk2++) {
            int row = gk2 * 16 + ((lane >> 4) << 3) + (lane & 7);
            int ch  = 2 * j + ((lane >> 3) & 1);
            uint32_t ah = kbb + row * 128 + ((ch ^ (row & 7)) << 4);
            uint32_t kh4[4], kl4[4];
            ldsm_x4(kh4, ah);
            ldsm_x4(kl4, ah + 4096);
            mma16816(sfr[2 * gk2],     qh[j], kh4);
            mma16816(sfr[2 * gk2 + 1], qh[j], kh4 + 2);
            mma16816(sfr[2 * gk2],     qh[j], kl4);
            mma16816(sfr[2 * gk2 + 1], qh[j], kl4 + 2);
            mma16816(sfr[2 * gk2],     ql[j], kh4);
            mma16816(sfr[2 * gk2 + 1], ql[j], kh4 + 2);
        }
    }
}

__device__ __forceinline__ void addbias32(float (*sfr)[4], int kb, int qrow,
        const float* __restrict__ maskb, const float* __restrict__ biash, int tc)
{
    #pragma unroll
    for (int grp = 0; grp < 4; grp++) {
        int key0 = kb + grp * 8 + tc * 2;
        float mv0 = (key0 >= PFX)     ? maskb[key0 - PFX]     : 0.f;
        float mv1 = (key0 + 1 >= PFX) ? maskb[key0 + 1 - PFX] : 0.f;
        const float* bp = biash + (key0 - qrow + (BIAS_OFF - PFX));
        sfr[grp][0] += bp[0] + mv0;
        sfr[grp][1] += bp[1] + mv1;
        sfr[grp][2] += bp[-8] + mv0;
        sfr[grp][3] += bp[-7] + mv1;
    }
}

template <int NG>
__device__ __forceinline__ void softmax_groups(float (*sfr)[4],
        float* mrow, float* lrow, float (*ofr)[4])
{
    #pragma unroll
    for (int row = 0; row < 2; row++) {
        float mx = sfr[0][row * 2];
        #pragma unroll
        for (int grp = 0; grp < NG; grp++) {
            mx = fmaxf(mx, sfr[grp][row * 2]);
            mx = fmaxf(mx, sfr[grp][row * 2 + 1]);
        }
        mx = fmaxf(mx, __shfl_xor_sync(0xffffffffu, mx, 1));
        mx = fmaxf(mx, __shfl_xor_sync(0xffffffffu, mx, 2));
        float mn = fmaxf(mrow[row], mx);
        float alpha = __expf(mrow[row] - mn);
        mrow[row] = mn;
        float sum = 0.f;
        #pragma unroll
        for (int grp = 0; grp < NG; grp++) {
            float p0 = __expf(sfr[grp][row * 2] - mn);
            float p1 = __expf(sfr[grp][row * 2 + 1] - mn);
            sfr[grp][row * 2] = p0;
            sfr[grp][row * 2 + 1] = p1;
            sum += p0 + p1;
        }
        sum += __shfl_xor_sync(0xffffffffu, sum, 1);
        sum += __shfl_xor_sync(0xffffffffu, sum, 2);
        lrow[row] = lrow[row] * alpha + sum;
        #pragma unroll
        for (int gd = 0; gd < 8; gd++) {
            ofr[gd][row * 2]     *= alpha;
            ofr[gd][row * 2 + 1] *= alpha;
        }
    }
}

__device__ __forceinline__ void pv32(float (*ofr)[4], const float (*sfr)[4],
                                     uint32_t vbb, int lane)
{
    uint32_t phi[2][4], plo[2][4];
    #pragma unroll
    for (int jk = 0; jk < 2; jk++) {
        #pragma unroll
        for (int e = 0; e < 4; e++) {
            int grp = 2 * jk + (e >> 1);
            int i0  = (e & 1) * 2;
            float p0 = sfr[grp][i0], p1 = sfr[grp][i0 + 1];
            __nv_bfloat16 h0 = __float2bfloat16(p0), h1 = __float2bfloat16(p1);
            phi[jk][e] = pkb2(h0, h1);
            plo[jk][e] = pkb2(__float2bfloat16(p0 - __bfloat162float(h0)),
                              __float2bfloat16(p1 - __bfloat162float(h1)));
        }
    }
    #pragma unroll
    for (int jk = 0; jk < 2; jk++) {
        #pragma unroll
        for (int gd2 = 0; gd2 < 4; gd2++) {
            int row = jk * 16 + (((lane >> 3) & 1) << 3) + (lane & 7);
            int ch  = 2 * gd2 + (lane >> 4);
            uint32_t av = vbb + row * 128 + ((ch ^ (row & 7)) << 4);
            uint32_t vh4[4], vl4[4];
            ldsm_x4_t(vh4, av);
            ldsm_x4_t(vl4, av + 4096);
            mma16816(ofr[2 * gd2],     phi[jk], vh4);
            mma16816(ofr[2 * gd2 + 1], phi[jk], vh4 + 2);
            mma16816(ofr[2 * gd2],     phi[jk], vl4);
            mma16816(ofr[2 * gd2 + 1], phi[jk], vl4 + 2);
            mma16816(ofr[2 * gd2],     plo[jk], vh4);
            mma16816(ofr[2 * gd2 + 1], plo[jk], vh4 + 2);
        }
    }
}

__global__ __launch_bounds__(128, 3) void attn_mma_kernel(const float* __restrict__ mask)
{
    extern __shared__ char kvsm[];
    uint32_t sb0 = smem_u32(kvsm);
    const int t = threadIdx.x, lane = t & 31, w = t >> 5;
    const int g = lane >> 2, tc = lane & 3;
    const int h = blockIdx.y, b = blockIdx.z, bh = b * HH + h;
    const int qb = blockIdx.x * 64;
    const int m0 = qb + w * 16;

    uint32_t qh[4][4], ql[4][4];
    {
        const __nv_bfloat16* qhp = g_qh + ((size_t)bh * SS + m0) * DH;
        const __nv_bfloat16* qlp = g_ql + ((size_t)bh * SS + m0) * DH;
        #pragma unroll
        for (int j = 0; j < 4; j++)
            #pragma unroll
            for (int e = 0; e < 4; e++) {
                int r = g + (e & 1) * 8;
                int k = j * 16 + tc * 2 + (e >> 1) * 8;
                qh[j][e] = *(const uint32_t*)(qhp + (size_t)r * DH + k);
                ql[j][e] = *(const uint32_t*)(qlp + (size_t)r * DH + k);
            }
    }

    float ofr[8][4];
    #pragma unroll
    for (int i = 0; i < 8; i++)
        #pragma unroll
        for (int e = 0; e < 4; e++) ofr[i][e] = 0.f;
    float mrow[2] = {-INFINITY, -INFINITY};
    float lrow[2] = {0.f, 0.f};

    const float* maskb = mask + b * SS;
    const float* biash = g_bias + h * BIAS_STRIDE;

    attn_load_kv_nc(t, bh, 0, sb0);             CP_COMMIT();
    attn_load_kv_nc(t, bh, 1, sb0 + 16384);     CP_COMMIT();
    attn_load_kv_nc(t, bh, 2, sb0 + 32768);     CP_COMMIT();

    float sfr[8][4];

    // ---- solo tile 0 (prefix region) ----
    asm volatile("cp.async.wait_group 2;" ::: "memory");
    __syncthreads();
    #pragma unroll
    for (int i = 0; i < 4; i++)
        #pragma unroll
        for (int e = 0; e < 4; e++) sfr[i][e] = 0.f;
    qk32(sfr, sb0, qh, ql, lane);
    addbias32(sfr, 0, m0 + g, maskb, biash, tc);
    softmax_groups<4>(sfr, mrow, lrow, ofr);
    pv32(ofr, sfr, sb0 + 8192, lane);

    // ---- 32 pairs: tiles (2p+1, 2p+2) ----
    for (int p = 0; p < 32; p++) {
        const int ta = 2 * p + 1, tb = 2 * p + 2;
        const uint32_t ba = sb0 + (ta & 3) * 16384;
        const uint32_t bbb = sb0 + (tb & 3) * 16384;
        __syncthreads();
        if (p < 31) {
            attn_load_kv_nc(t, bh, 2 * p + 3, sb0 + ((2 * p + 3) & 3) * 16384);
            attn_load_kv_nc(t, bh, 2 * p + 4, sb0 + ((2 * p + 4) & 3) * 16384);
            CP_COMMIT();
            asm volatile("cp.async.wait_group 1;" ::: "memory");
        } else {
            asm volatile("cp.async.wait_group 0;" ::: "memory");
        }
        __syncthreads();

        #pragma unroll
        for (int i = 0; i < 8; i++)
            #pragma unroll
            for (int e = 0; e < 4; e++) sfr[i][e] = 0.f;
        qk32(sfr,     ba,  qh, ql, lane);
        qk32(sfr + 4, bbb, qh, ql, lane);
        addbias32(sfr,     ta * 32, m0 + g, maskb, biash, tc);
        addbias32(sfr + 4, tb * 32, m0 + g, maskb, biash, tc);
        softmax_groups<8>(sfr, mrow, lrow, ofr);
        pv32(ofr, sfr,     ba  + 8192, lane);
        pv32(ofr, sfr + 4, bbb + 8192, lane);
    }

    // ---- epilogue: normalize, split hi/lo, write g_oh / g_ol ----
    float inv0 = 1.f / lrow[0], inv1 = 1.f / lrow[1];
    #pragma unroll
    for (int gd = 0; gd < 8; gd++) {
        int d0 = gd * 8 + tc * 2;
        int k  = h * 64 + d0;
        #pragma unroll
        for (int row = 0; row < 2; row++) {
            float v0 = ofr[gd][row * 2]     * (row ? inv1 : inv0);
            float v1 = ofr[gd][row * 2 + 1] * (row ? inv1 : inv0);
            __nv_bfloat16 h0 = __float2bfloat16(v0), h1 = __float2bfloat16(v1);
            uint32_t hi = pkb2(h0, h1);
            uint32_t lo = pkb2(__float2bfloat16(v0 - __bfloat162float(h0)),
                               __float2bfloat16(v1 - __bfloat162float(h1)));
            size_t rbase = ((size_t)(b * SS + m0 + g + row * 8)) * DDIM + k;
            *(uint32_t*)(g_oh + rbase) = hi;
            *(uint32_t*)(g_ol + rbase) = lo;
        }
    }
}

// ---------------- launch ----------------
extern "C" void kernel_launch(void* const* d_in, const int* in_sizes, int n_in,
                              void* d_out, int out_size)
{
    const float* hidden = (const float*)d_in[0];
    const float* mask   = (const float*)d_in[1];
    const float* pk     = (const float*)d_in[2];
    const float* pv     = (const float*)d_in[3];
    const float* Wq     = (const float*)d_in[4];
    const float* Wk     = (const float*)d_in[5];
    const float* Wv     = (const float*)d_in[6];
    const float* Wo     = (const float*)d_in[7];
    const float* rel    = (const float*)d_in[8];
    float* out = (float*)d_out;

    cudaFuncSetAttribute(attn_mma_kernel,
                         cudaFuncAttributeMaxDynamicSharedMemorySize, ATTN_SMEM);
    cudaFuncSetAttribute(gemm_qkv_mma,
                         cudaFuncAttributeMaxDynamicSharedMemorySize, GEMM_SMEM);
    cudaFuncSetAttribute(gemm_o_mma,
                         cudaFuncAttributeMaxDynamicSharedMemorySize, GEMM_SMEM);

    prep_kernel<<<PREP_BLOCKS, 256>>>(hidden, Wq, Wk, Wv, Wo, pk, pv, rel);
    gemm_qkv_mma<<<dim3(8, 32, 3), 256, GEMM_SMEM>>>();
    attn_mma_kernel<<<dim3(SS / 64, HH, BB), 128, ATTN_SMEM>>>(mask);
    gemm_o_mma<<<dim3(8, 32), 256, GEMM_SMEM>>>(out);
}

// round 14
// speedup vs baseline: 1.0494x; 1.0494x over previous
#include <cuda_runtime.h>
#include <cuda_bf16.h>
#include <math.h>
#include <stdint.h>

// Problem constants
#define BB   2
#define HH   16
#define SS   2048
#define DDIM 1024
#define DH   64
#define PFX  32
#define LKV  2080          // PFX + SS = 65 * 32
#define BIAS_STRIDE 4160
#define BIAS_OFF 2079

// ---------------- scratch (static device globals; no allocation) ----------------
__device__ float g_bias[HH * BIAS_STRIDE];                   // [h][rel+2079]
__device__ __nv_bfloat16 g_ah[(size_t)BB * SS * DDIM];       // hidden hi [m][k]
__device__ __nv_bfloat16 g_al[(size_t)BB * SS * DDIM];       // hidden lo
__device__ __nv_bfloat16 g_wh[(size_t)4 * DDIM * DDIM];      // W hi, transposed [n][k]
__device__ __nv_bfloat16 g_wl[(size_t)4 * DDIM * DDIM];      // W lo
__device__ __nv_bfloat16 g_oh[(size_t)BB * SS * DDIM];       // attn-out hi
__device__ __nv_bfloat16 g_ol[(size_t)BB * SS * DDIM];       // attn-out lo
__device__ __nv_bfloat16 g_qh[(size_t)BB * HH * SS * DH];    // [bh][s][d]
__device__ __nv_bfloat16 g_ql[(size_t)BB * HH * SS * DH];
__device__ __nv_bfloat16 g_kh[(size_t)BB * HH * LKV * DH];   // [bh][key][d]
__device__ __nv_bfloat16 g_kl[(size_t)BB * HH * LKV * DH];
__device__ __nv_bfloat16 g_vh[(size_t)BB * HH * LKV * DH];
__device__ __nv_bfloat16 g_vl[(size_t)BB * HH * LKV * DH];

// ======================= PTX helpers (sm_80-class only) =======================
__device__ __forceinline__ uint32_t smem_u32(const void* p) {
    uint32_t a;
    asm("{ .reg .u64 t; cvta.to.shared.u64 t, %1; cvt.u32.u64 %0, t; }" : "=r"(a) : "l"(p));
    return a;
}
__device__ __forceinline__ void cpa16(uint32_t dst, const void* src) {
    asm volatile("cp.async.cg.shared.global [%0], [%1], 16;" :: "r"(dst), "l"(src));
}
__device__ __forceinline__ void ldsm_x4(uint32_t* r, uint32_t addr) {
    asm volatile("ldmatrix.sync.aligned.m8n8.x4.shared.b16 {%0,%1,%2,%3}, [%4];"
                 : "=r"(r[0]), "=r"(r[1]), "=r"(r[2]), "=r"(r[3]) : "r"(addr));
}
__device__ __forceinline__ void ldsm_x4_t(uint32_t* r, uint32_t addr) {
    asm volatile("ldmatrix.sync.aligned.m8n8.x4.trans.shared.b16 {%0,%1,%2,%3}, [%4];"
                 : "=r"(r[0]), "=r"(r[1]), "=r"(r[2]), "=r"(r[3]) : "r"(addr));
}
__device__ __forceinline__ void mma16816(float* d, const uint32_t* a, const uint32_t* b) {
    asm volatile("mma.sync.aligned.m16n8k16.row.col.f32.bf16.bf16.f32 "
                 "{%0,%1,%2,%3}, {%4,%5,%6,%7}, {%8,%9}, {%0,%1,%2,%3};"
                 : "+f"(d[0]), "+f"(d[1]), "+f"(d[2]), "+f"(d[3])
                 : "r"(a[0]), "r"(a[1]), "r"(a[2]), "r"(a[3]), "r"(b[0]), "r"(b[1]));
}
__device__ __forceinline__ uint32_t pkb2(__nv_bfloat16 a, __nv_bfloat16 b) {
    uint16_t ua = *(uint16_t*)&a, ub = *(uint16_t*)&b;
    return (uint32_t)ua | ((uint32_t)ub << 16);
}
// 128B-row swizzled smem element address
__device__ __forceinline__ uint32_t sw_addr128(uint32_t base, int r, int k) {
    int quad = k >> 3;
    int sw   = quad ^ (r & 7);
    return base + r * 128 + sw * 16 + (k & 7) * 2;
}
#define CP_COMMIT() asm volatile("cp.async.commit_group;" ::: "memory")

// ---------------- fused preprocessing kernel ----------------
#define PREP_BLOCKS 8706

__global__ __launch_bounds__(256) void prep_kernel(
        const float* __restrict__ hidden,
        const float* __restrict__ Wq, const float* __restrict__ Wk,
        const float* __restrict__ Wv, const float* __restrict__ Wo,
        const float* __restrict__ pk, const float* __restrict__ pv,
        const float* __restrict__ rel_table)
{
    __shared__ float tile[32][33];
    const int bid = blockIdx.x;
    const int tid = threadIdx.x;

    if (bid < 4096) {
        int i4 = bid * 256 + tid;
        float4 x = *(const float4*)(hidden + (size_t)i4 * 4);
        __nv_bfloat16 h0 = __float2bfloat16(x.x), h1 = __float2bfloat16(x.y);
        __nv_bfloat16 h2 = __float2bfloat16(x.z), h3 = __float2bfloat16(x.w);
        uint32_t hiA = pkb2(h0, h1), hiB = pkb2(h2, h3);
        uint32_t loA = pkb2(__float2bfloat16(x.x - __bfloat162float(h0)),
                            __float2bfloat16(x.y - __bfloat162float(h1)));
        uint32_t loB = pkb2(__float2bfloat16(x.z - __bfloat162float(h2)),
                            __float2bfloat16(x.w - __bfloat162float(h3)));
        size_t b = (size_t)i4 * 4;
        uint32_t* ph = (uint32_t*)(g_ah + b);
        ph[0] = hiA; ph[1] = hiB;
        uint32_t* pl = (uint32_t*)(g_al + b);
        pl[0] = loA; pl[1] = loB;
    } else if (bid < 8192) {
        int zz = bid - 4096;
        int z  = zz >> 10;
        int zb = zz & 1023;
        int n0 = (zb & 31) * 32, k0 = (zb >> 5) * 32;
        const float* W = (z == 0) ? Wq : (z == 1) ? Wk : (z == 2) ? Wv : Wo;
        __nv_bfloat16* dh = g_wh + (size_t)z * DDIM * DDIM;
        __nv_bfloat16* dl = g_wl + (size_t)z * DDIM * DDIM;
        const int tx = tid & 31, ty0 = tid >> 5;
        #pragma unroll
        for (int r = 0; r < 4; r++) {
            int ty = ty0 + r * 8;
            tile[ty][tx] = W[(size_t)(k0 + ty) * DDIM + n0 + tx];
        }
        __syncthreads();
        #pragma unroll
        for (int r = 0; r < 4; r++) {
            int ty = ty0 + r * 8;
            float x = tile[tx][ty];
            __nv_bfloat16 h = __float2bfloat16(x);
            __nv_bfloat16 l = __float2bfloat16(x - __bfloat162float(h));
            size_t b = (size_t)(n0 + ty) * DDIM + (k0 + tx);
            dh[b] = h;
            dl[b] = l;
        }
    } else if (bid < 8450) {
        int idx = (bid - 8192) * 256 + tid;
        if (idx < HH * 4127) {
            int h   = idx / 4127;
            int r   = idx - h * 4127;
            int rel = r - BIAS_OFF;
            int ret = (rel > 0) ? 16 : 0;
            int n   = rel < 0 ? -rel : rel;
            int bkt;
            if (n < 8) {
                bkt = n;
            } else {
                float nf = (float)n;
                int vl = 8 + (int)(logf(nf * 0.125f) / 2.772588722239781f * 8.0f);
                bkt = vl < 15 ? vl : 15;
            }
            bkt += ret;
            g_bias[h * BIAS_STRIDE + r] = rel_table[bkt * HH + h];
        }
    } else {
        int idx = (bid - 8450) * 256 + tid;
        int d  = idx & 63;
        int p  = (idx >> 6) & 31;
        int bh = idx >> 11;
        size_t o = ((size_t)bh * LKV + p) * DH + d;
        float kx = pk[idx], vx = pv[idx];
        __nv_bfloat16 khf = __float2bfloat16(kx);
        __nv_bfloat16 vhf = __float2bfloat16(vx);
        g_kh[o] = khf;
        g_kl[o] = __float2bfloat16(kx - __bfloat162float(khf));
        g_vh[o] = vhf;
        g_vl[o] = __float2bfloat16(vx - __bfloat162float(vhf));
    }
}

// ---------------- mma.sync bf16 GEMM: C = [Ahi|Ahi|Alo] * [Whi|Wlo|Whi]^T ----------------
// CHUNK=64 (128B rows), NSTG=3 (96KB dyn smem), NCH=48.
// Per-warp k-step rotation ((w&3)) forces ldsm/mma anti-phase across warps.
#define CHUNK 64
#define NSTG 3
#define STG_BYTES 32768
#define NCH 48
#define GEMM_SMEM (NSTG * STG_BYTES)

__device__ __forceinline__ void gemm_load_chunk(uint32_t sb,
        const __nv_bfloat16* __restrict__ Ah, const __nv_bfloat16* __restrict__ Al,
        const __nv_bfloat16* __restrict__ Wh, const __nv_bfloat16* __restrict__ Wl,
        int mblock, int nblock, int c)
{
    const int t = threadIdx.x;
    const int st = c % NSTG;
    uint32_t ab = sb + st * STG_BYTES;
    uint32_t bb = ab + 16384;
    const __nv_bfloat16* Ag = (c < 32) ? Ah : Al;
    const __nv_bfloat16* Wg = (c < 16 || c >= 32) ? Wh : Wl;
    const int co = (c & 15) * CHUNK;
    #pragma unroll
    for (int i = 0; i < 4; i++) {
        int idx = t + i * 256;
        int r = idx >> 3, q = idx & 7;
        uint32_t soff = (uint32_t)(r * 128 + ((q ^ (r & 7)) << 4));
        const char* as = (const char*)(Ag + (size_t)(mblock + r) * DDIM + co + q * 8);
        const char* bs = (const char*)(Wg + (size_t)(nblock + r) * DDIM + co + q * 8);
        cpa16(ab + soff, as);
        cpa16(bb + soff, bs);
    }
    CP_COMMIT();
}

__device__ __forceinline__ void gemm_mma_body(
        const __nv_bfloat16* __restrict__ Ah, const __nv_bfloat16* __restrict__ Al,
        const __nv_bfloat16* __restrict__ Wh, const __nv_bfloat16* __restrict__ Wl,
        int mblock, int nblock, int flavor, float* __restrict__ outp)
{
    extern __shared__ __align__(128) char smbuf[];
    uint32_t sb = smem_u32(smbuf);
    const int t    = threadIdx.x;
    const int lane = t & 31;
    const int w    = t >> 5;
    const int wm   = w >> 1;
    const int wn   = w & 1;
    const int kso  = w & 3;            // per-warp k-step rotation

    float acc[2][8][4];
    #pragma unroll
    for (int f = 0; f < 2; f++)
        #pragma unroll
        for (int p = 0; p < 8; p++)
            #pragma unroll
            for (int e = 0; e < 4; e++) acc[f][p][e] = 0.f;

    gemm_load_chunk(sb, Ah, Al, Wh, Wl, mblock, nblock, 0);
    gemm_load_chunk(sb, Ah, Al, Wh, Wl, mblock, nblock, 1);

    for (int c = 0; c < NCH; c++) {
        if (c < NCH - 1) asm volatile("cp.async.wait_group 1;" ::: "memory");
        else             asm volatile("cp.async.wait_group 0;" ::: "memory");
        __syncthreads();
        // stage (c+2)%3 == (c-1)%3: its readers finished at iter c-1 (barrier above)
        if (c + 2 < NCH) gemm_load_chunk(sb, Ah, Al, Wh, Wl, mblock, nblock, c + 2);

        uint32_t ab = sb + (c % NSTG) * STG_BYTES;
        uint32_t bb = ab + 16384;

        #pragma unroll
        for (int ks2 = 0; ks2 < 4; ks2++) {
            const int ks = (ks2 + kso) & 3;    // rotated order; all 4 steps resident
            uint32_t afr[2][4];
            #pragma unroll
            for (int f = 0; f < 2; f++) {
                int r = wm * 32 + f * 16 + (lane & 15);
                int k = ks * 16 + (lane >> 4) * 8;
                ldsm_x4(afr[f], sw_addr128(ab, r, k));
            }
            uint32_t bfr[8][2];
            #pragma unroll
            for (int p = 0; p < 4; p++) {
                int n = wn * 64 + p * 16 + ((lane >> 4) & 1) * 8 + (lane & 7);
                int k = ks * 16 + ((lane >> 3) & 1) * 8;
                uint32_t r4[4];
                ldsm_x4(r4, sw_addr128(bb, n, k));
                bfr[p * 2][0]     = r4[0];
                bfr[p * 2][1]     = r4[1];
                bfr[p * 2 + 1][0] = r4[2];
                bfr[p * 2 + 1][1] = r4[3];
            }
            #pragma unroll
            for (int f = 0; f < 2; f++)
                #pragma unroll
                for (int p = 0; p < 8; p++)
                    mma16816(acc[f][p], afr[f], bfr[p]);
        }
    }

    #pragma unroll
    for (int f = 0; f < 2; f++) {
        #pragma unroll
        for (int p = 0; p < 8; p++) {
            #pragma unroll
            for (int e2 = 0; e2 < 2; e2++) {
                int m  = mblock + wm * 32 + f * 16 + (lane >> 2) + e2 * 8;
                int n0 = nblock + wn * 64 + p * 8 + ((lane & 3) << 1);
                float v0 = acc[f][p][e2 * 2], v1 = acc[f][p][e2 * 2 + 1];
                if (flavor == 3) {
                    outp[(size_t)m * DDIM + n0]     = v0;
                    outp[(size_t)m * DDIM + n0 + 1] = v1;
                } else {
                    __nv_bfloat16 h0 = __float2bfloat16(v0), h1 = __float2bfloat16(v1);
                    uint32_t hi = pkb2(h0, h1);
                    uint32_t lo = pkb2(__float2bfloat16(v0 - __bfloat162float(h0)),
                                       __float2bfloat16(v1 - __bfloat162float(h1)));
                    int b0 = m >> 11, s = m & 2047, hh = n0 >> 6, d = n0 & 63;
                    int bh = b0 * HH + hh;
                    if (flavor == 0) {
                        size_t o = ((size_t)bh * SS + s) * DH + d;
                        *(uint32_t*)(g_qh + o) = hi;
                        *(uint32_t*)(g_ql + o) = lo;
                    } else {
                        size_t o = ((size_t)bh * LKV + PFX + s) * DH + d;
                        if (flavor == 1) {
                            *(uint32_t*)(g_kh + o) = hi;
                            *(uint32_t*)(g_kl + o) = lo;
                        } else {
                            *(uint32_t*)(g_vh + o) = hi;
                            *(uint32_t*)(g_vl + o) = lo;
                        }
                    }
                }
            }
        }
    }
}

__global__ __launch_bounds__(256, 2) void gemm_qkv_mma()
{
    const int z = blockIdx.z;
    gemm_mma_body(g_ah, g_al,
                  g_wh + (size_t)z * DDIM * DDIM, g_wl + (size_t)z * DDIM * DDIM,
                  blockIdx.y * 128, blockIdx.x * 128, z, nullptr);
}

__global__ __launch_bounds__(256, 2) void gemm_o_mma(float* __restrict__ out)
{
    gemm_mma_body(g_oh, g_ol,
                  g_wh + (size_t)3 * DDIM * DDIM, g_wl + (size_t)3 * DDIM * DDIM,
                  blockIdx.y * 128, blockIdx.x * 128, 3, out);
}

// ---------------- mma.sync flash attention (paired 64-key softmax) ----------------
#define ATTN_SMEM 65536

__device__ __forceinline__ void attn_load_kv_nc(int t, int bh, int kt, uint32_t base)
{
    #pragma unroll
    for (int i = 0; i < 2; i++) {
        const int row = (t >> 3) + i * 16;
        const int c = t & 7;
        uint32_t off = (uint32_t)(row * 128 + ((c ^ (row & 7)) << 4));
        size_t goff = ((size_t)bh * LKV + kt * 32 + row) * DH + c * 8;
        cpa16(base + off,         g_kh + goff);
        cpa16(base + 4096 + off,  g_kl + goff);
        cpa16(base + 8192 + off,  g_vh + goff);
        cpa16(base + 12288 + off, g_vl + goff);
    }
}

__device__ __forceinline__ void qk32(float (*sfr)[4], uint32_t kbb,
        const uint32_t (*qh)[4], const uint32_t (*ql)[4], int lane)
{
    #pragma unroll
    for (int j = 0; j < 4; j++) {
        #pragma unroll
        for (int gk2 = 0; gk2 < 2; gk2++) {
            int row = gk2 * 16 + ((lane >> 4) << 3) + (lane & 7);
            int ch  = 2 * j + ((lane >> 3) & 1);
            uint32_t ah = kbb + row * 128 + ((ch ^ (row & 7)) << 4);
            uint32_t kh4[4], kl4[4];
            ldsm_x4(kh4, ah);
            ldsm_x4(kl4, ah + 4096);
            mma16816(sfr[2 * gk2],     qh[j], kh4);
            mma16816(sfr[2 * gk2 + 1], qh[j], kh4 + 2);
            mma16816(sfr[2 * gk2],     qh[j], kl4);
            mma16816(sfr[2 * gk2 + 1], qh[j], kl4 + 2);
            mma16816(sfr[2 * gk2],     ql[j], kh4);
            mma16816(sfr[2 * gk2 + 1], ql[j], kh4 + 2);
        }
    }
}

__device__ __forceinline__ void addbias32(float (*sfr)[4], int kb, int qrow,
        const float* __restrict__ maskb, const float* __restrict__ biash, int tc)
{
    #pragma unroll
    for (int grp = 0; grp < 4; grp++) {
        int key0 = kb + grp * 8 + tc * 2;
        float mv0 = (key0 >= PFX)     ? maskb[key0 - PFX]     : 0.f;
        float mv1 = (key0 + 1 >= PFX) ? maskb[key0 + 1 - PFX] : 0.f;
        const float* bp = biash + (key0 - qrow + (BIAS_OFF - PFX));
        sfr[grp][0] += bp[0] + mv0;
        sfr[grp][1] += bp[1] + mv1;
        sfr[grp][2] += bp[-8] + mv0;
        sfr[grp][3] += bp[-7] + mv1;
    }
}

template <int NG>
__device__ __forceinline__ void softmax_groups(float (*sfr)[4],
        float* mrow, float* lrow, float (*ofr)[4])
{
    #pragma unroll
    for (int row = 0; row < 2; row++) {
        float mx = sfr[0][row * 2];
        #pragma unroll
        for (int grp = 0; grp < NG; grp++) {
            mx = fmaxf(mx, sfr[grp][row * 2]);
            mx = fmaxf(mx, sfr[grp][row * 2 + 1]);
        }
        mx = fmaxf(mx, __shfl_xor_sync(0xffffffffu, mx, 1));
        mx = fmaxf(mx, __shfl_xor_sync(0xffffffffu, mx, 2));
        float mn = fmaxf(mrow[row], mx);
        float alpha = __expf(mrow[row] - mn);
        mrow[row] = mn;
        float sum = 0.f;
        #pragma unroll
        for (int grp = 0; grp < NG; grp++) {
            float p0 = __expf(sfr[grp][row * 2] - mn);
            float p1 = __expf(sfr[grp][row * 2 + 1] - mn);
            sfr[grp][row * 2] = p0;
            sfr[grp][row * 2 + 1] = p1;
            sum += p0 + p1;
        }
        sum += __shfl_xor_sync(0xffffffffu, sum, 1);
        sum += __shfl_xor_sync(0xffffffffu, sum, 2);
        lrow[row] = lrow[row] * alpha + sum;
        #pragma unroll
        for (int gd = 0; gd < 8; gd++) {
            ofr[gd][row * 2]     *= alpha;
            ofr[gd][row * 2 + 1] *= alpha;
        }
    }
}

__device__ __forceinline__ void pv32(float (*ofr)[4], const float (*sfr)[4],
                                     uint32_t vbb, int lane)
{
    uint32_t phi[2][4], plo[2][4];
    #pragma unroll
    for (int jk = 0; jk < 2; jk++) {
        #pragma unroll
        for (int e = 0; e < 4; e++) {
            int grp = 2 * jk + (e >> 1);
            int i0  = (e & 1) * 2;
            float p0 = sfr[grp][i0], p1 = sfr[grp][i0 + 1];
            __nv_bfloat16 h0 = __float2bfloat16(p0), h1 = __float2bfloat16(p1);
            phi[jk][e] = pkb2(h0, h1);
            plo[jk][e] = pkb2(__float2bfloat16(p0 - __bfloat162float(h0)),
                              __float2bfloat16(p1 - __bfloat162float(h1)));
        }
    }
    #pragma unroll
    for (int jk = 0; jk < 2; jk++) {
        #pragma unroll
        for (int gd2 = 0; gd2 < 4; gd2++) {
            int row = jk * 16 + (((lane >> 3) & 1) << 3) + (lane & 7);
            int ch  = 2 * gd2 + (lane >> 4);
            uint32_t av = vbb + row * 128 + ((ch ^ (row & 7)) << 4);
            uint32_t vh4[4], vl4[4];
            ldsm_x4_t(vh4, av);
            ldsm_x4_t(vl4, av + 4096);
            mma16816(ofr[2 * gd2],     phi[jk], vh4);
            mma16816(ofr[2 * gd2 + 1], phi[jk], vh4 + 2);
            mma16816(ofr[2 * gd2],     phi[jk], vl4);
            mma16816(ofr[2 * gd2 + 1], phi[jk], vl4 + 2);
            mma16816(ofr[2 * gd2],     plo[jk], vh4);
            mma16816(ofr[2 * gd2 + 1], plo[jk], vh4 + 2);
        }
    }
}

__global__ __launch_bounds__(128, 3) void attn_mma_kernel(const float* __restrict__ mask)
{
    extern __shared__ char kvsm[];
    uint32_t sb0 = smem_u32(kvsm);
    const int t = threadIdx.x, lane = t & 31, w = t >> 5;
    const int g = lane >> 2, tc = lane & 3;
    const int h = blockIdx.y, b = blockIdx.z, bh = b * HH + h;
    const int qb = blockIdx.x * 64;
    const int m0 = qb + w * 16;

    uint32_t qh[4][4], ql[4][4];
    {
        const __nv_bfloat16* qhp = g_qh + ((size_t)bh * SS + m0) * DH;
        const __nv_bfloat16* qlp = g_ql + ((size_t)bh * SS + m0) * DH;
        #pragma unroll
        for (int j = 0; j < 4; j++)
            #pragma unroll
            for (int e = 0; e < 4; e++) {
                int r = g + (e & 1) * 8;
                int k = j * 16 + tc * 2 + (e >> 1) * 8;
                qh[j][e] = *(const uint32_t*)(qhp + (size_t)r * DH + k);
                ql[j][e] = *(const uint32_t*)(qlp + (size_t)r * DH + k);
            }
    }

    float ofr[8][4];
    #pragma unroll
    for (int i = 0; i < 8; i++)
        #pragma unroll
        for (int e = 0; e < 4; e++) ofr[i][e] = 0.f;
    float mrow[2] = {-INFINITY, -INFINITY};
    float lrow[2] = {0.f, 0.f};

    const float* maskb = mask + b * SS;
    const float* biash = g_bias + h * BIAS_STRIDE;

    attn_load_kv_nc(t, bh, 0, sb0);             CP_COMMIT();
    attn_load_kv_nc(t, bh, 1, sb0 + 16384);     CP_COMMIT();
    attn_load_kv_nc(t, bh, 2, sb0 + 32768);     CP_COMMIT();

    float sfr[8][4];

    // ---- solo tile 0 (prefix region) ----
    asm volatile("cp.async.wait_group 2;" ::: "memory");
    __syncthreads();
    #pragma unroll
    for (int i = 0; i < 4; i++)
        #pragma unroll
        for (int e = 0; e < 4; e++) sfr[i][e] = 0.f;
    qk32(sfr, sb0, qh, ql, lane);
    addbias32(sfr, 0, m0 + g, maskb, biash, tc);
    softmax_groups<4>(sfr, mrow, lrow, ofr);
    pv32(ofr, sfr, sb0 + 8192, lane);

    // ---- 32 pairs: tiles (2p+1, 2p+2) ----
    for (int p = 0; p < 32; p++) {
        const int ta = 2 * p + 1, tb = 2 * p + 2;
        const uint32_t ba = sb0 + (ta & 3) * 16384;
        const uint32_t bbb = sb0 + (tb & 3) * 16384;
        __syncthreads();
        if (p < 31) {
            attn_load_kv_nc(t, bh, 2 * p + 3, sb0 + ((2 * p + 3) & 3) * 16384);
            attn_load_kv_nc(t, bh, 2 * p + 4, sb0 + ((2 * p + 4) & 3) * 16384);
            CP_COMMIT();
            asm volatile("cp.async.wait_group 1;" ::: "memory");
        } else {
            asm volatile("cp.async.wait_group 0;" ::: "memory");
        }
        __syncthreads();

        #pragma unroll
        for (int i = 0; i < 8; i++)
            #pragma unroll
            for (int e = 0; e < 4; e++) sfr[i][e] = 0.f;
        qk32(sfr,     ba,  qh, ql, lane);
        qk32(sfr + 4, bbb, qh, ql, lane);
        addbias32(sfr,     ta * 32, m0 + g, maskb, biash, tc);
        addbias32(sfr + 4, tb * 32, m0 + g, maskb, biash, tc);
        softmax_groups<8>(sfr, mrow, lrow, ofr);
        pv32(ofr, sfr,     ba  + 8192, lane);
        pv32(ofr, sfr + 4, bbb + 8192, lane);
    }

    // ---- epilogue: normalize, split hi/lo, write g_oh / g_ol ----
    float inv0 = 1.f / lrow[0], inv1 = 1.f / lrow[1];
    #pragma unroll
    for (int gd = 0; gd < 8; gd++) {
        int d0 = gd * 8 + tc * 2;
        int k  = h * 64 + d0;
        #pragma unroll
        for (int row = 0; row < 2; row++) {
            float v0 = ofr[gd][row * 2]     * (row ? inv1 : inv0);
            float v1 = ofr[gd][row * 2 + 1] * (row ? inv1 : inv0);
            __nv_bfloat16 h0 = __float2bfloat16(v0), h1 = __float2bfloat16(v1);
            uint32_t hi = pkb2(h0, h1);
            uint32_t lo = pkb2(__float2bfloat16(v0 - __bfloat162float(h0)),
                               __float2bfloat16(v1 - __bfloat162float(h1)));
            size_t rbase = ((size_t)(b * SS + m0 + g + row * 8)) * DDIM + k;
            *(uint32_t*)(g_oh + rbase) = hi;
            *(uint32_t*)(g_ol + rbase) = lo;
        }
    }
}

// ---------------- launch ----------------
extern "C" void kernel_launch(void* const* d_in, const int* in_sizes, int n_in,
                              void* d_out, int out_size)
{
    const float* hidden = (const float*)d_in[0];
    const float* mask   = (const float*)d_in[1];
    const float* pk     = (const float*)d_in[2];
    const float* pv     = (const float*)d_in[3];
    const float* Wq     = (const float*)d_in[4];
    const float* Wk     = (const float*)d_in[5];
    const float* Wv     = (const float*)d_in[6];
    const float* Wo     = (const float*)d_in[7];
    const float* rel    = (const float*)d_in[8];
    float* out = (float*)d_out;

    cudaFuncSetAttribute(attn_mma_kernel,
                         cudaFuncAttributeMaxDynamicSharedMemorySize, ATTN_SMEM);
    cudaFuncSetAttribute(gemm_qkv_mma,
                         cudaFuncAttributeMaxDynamicSharedMemorySize, GEMM_SMEM);
    cudaFuncSetAttribute(gemm_o_mma,
                         cudaFuncAttributeMaxDynamicSharedMemorySize, GEMM_SMEM);

    prep_kernel<<<PREP_BLOCKS, 256>>>(hidden, Wq, Wk, Wv, Wo, pk, pv, rel);
    gemm_qkv_mma<<<dim3(8, 32, 3), 256, GEMM_SMEM>>>();
    attn_mma_kernel<<<dim3(SS / 64, HH, BB), 128, ATTN_SMEM>>>(mask);
    gemm_o_mma<<<dim3(8, 32), 256, GEMM_SMEM>>>(out);
}

// round 15
// speedup vs baseline: 1.0742x; 1.0236x over previous
#include <cuda_runtime.h>
#include <cuda_bf16.h>
#include <math.h>
#include <stdint.h>

// Problem constants
#define BB   2
#define HH   16
#define SS   2048
#define DDIM 1024
#define DH   64
#define PFX  32
#define LKV  2080          // PFX + SS = 65 * 32
#define BIAS_STRIDE 4160
#define BIAS_OFF 2079

// ---------------- scratch (static device globals; no allocation) ----------------
__device__ float g_bias[HH * BIAS_STRIDE];                   // [h][rel+2079]
__device__ __nv_bfloat16 g_ah[(size_t)BB * SS * DDIM];       // hidden hi [m][k]
__device__ __nv_bfloat16 g_al[(size_t)BB * SS * DDIM];       // hidden lo
__device__ __nv_bfloat16 g_wh[(size_t)4 * DDIM * DDIM];      // W hi, transposed [n][k]
__device__ __nv_bfloat16 g_wl[(size_t)4 * DDIM * DDIM];      // W lo
__device__ __nv_bfloat16 g_oh[(size_t)BB * SS * DDIM];       // attn-out hi
__device__ __nv_bfloat16 g_ol[(size_t)BB * SS * DDIM];       // attn-out lo
__device__ __nv_bfloat16 g_qh[(size_t)BB * HH * SS * DH];    // [bh][s][d]
__device__ __nv_bfloat16 g_ql[(size_t)BB * HH * SS * DH];
__device__ __nv_bfloat16 g_kh[(size_t)BB * HH * LKV * DH];   // [bh][key][d]
__device__ __nv_bfloat16 g_kl[(size_t)BB * HH * LKV * DH];
__device__ __nv_bfloat16 g_vh[(size_t)BB * HH * LKV * DH];
__device__ __nv_bfloat16 g_vl[(size_t)BB * HH * LKV * DH];

// ======================= PTX helpers (sm_80-class only) =======================
__device__ __forceinline__ uint32_t smem_u32(const void* p) {
    uint32_t a;
    asm("{ .reg .u64 t; cvta.to.shared.u64 t, %1; cvt.u32.u64 %0, t; }" : "=r"(a) : "l"(p));
    return a;
}
__device__ __forceinline__ void cpa16(uint32_t dst, const void* src) {
    asm volatile("cp.async.cg.shared.global [%0], [%1], 16;" :: "r"(dst), "l"(src));
}
__device__ __forceinline__ void ldsm_x4(uint32_t* r, uint32_t addr) {
    asm volatile("ldmatrix.sync.aligned.m8n8.x4.shared.b16 {%0,%1,%2,%3}, [%4];"
                 : "=r"(r[0]), "=r"(r[1]), "=r"(r[2]), "=r"(r[3]) : "r"(addr));
}
__device__ __forceinline__ void ldsm_x4_t(uint32_t* r, uint32_t addr) {
    asm volatile("ldmatrix.sync.aligned.m8n8.x4.trans.shared.b16 {%0,%1,%2,%3}, [%4];"
                 : "=r"(r[0]), "=r"(r[1]), "=r"(r[2]), "=r"(r[3]) : "r"(addr));
}
__device__ __forceinline__ void mma16816(float* d, const uint32_t* a, const uint32_t* b) {
    asm volatile("mma.sync.aligned.m16n8k16.row.col.f32.bf16.bf16.f32 "
                 "{%0,%1,%2,%3}, {%4,%5,%6,%7}, {%8,%9}, {%0,%1,%2,%3};"
                 : "+f"(d[0]), "+f"(d[1]), "+f"(d[2]), "+f"(d[3])
                 : "r"(a[0]), "r"(a[1]), "r"(a[2]), "r"(a[3]), "r"(b[0]), "r"(b[1]));
}
__device__ __forceinline__ uint32_t pkb2(__nv_bfloat16 a, __nv_bfloat16 b) {
    uint16_t ua = *(uint16_t*)&a, ub = *(uint16_t*)&b;
    return (uint32_t)ua | ((uint32_t)ub << 16);
}
// 128B-row swizzled smem element address
__device__ __forceinline__ uint32_t sw_addr128(uint32_t base, int r, int k) {
    int quad = k >> 3;
    int sw   = quad ^ (r & 7);
    return base + r * 128 + sw * 16 + (k & 7) * 2;
}
#define CP_COMMIT() asm volatile("cp.async.commit_group;" ::: "memory")

// ---------------- fused preprocessing kernel ----------------
#define PREP_BLOCKS 8706

__global__ __launch_bounds__(256) void prep_kernel(
        const float* __restrict__ hidden,
        const float* __restrict__ Wq, const float* __restrict__ Wk,
        const float* __restrict__ Wv, const float* __restrict__ Wo,
        const float* __restrict__ pk, const float* __restrict__ pv,
        const float* __restrict__ rel_table)
{
    __shared__ float tile[32][33];
    const int bid = blockIdx.x;
    const int tid = threadIdx.x;

    if (bid < 4096) {
        int i4 = bid * 256 + tid;
        float4 x = *(const float4*)(hidden + (size_t)i4 * 4);
        __nv_bfloat16 h0 = __float2bfloat16(x.x), h1 = __float2bfloat16(x.y);
        __nv_bfloat16 h2 = __float2bfloat16(x.z), h3 = __float2bfloat16(x.w);
        uint32_t hiA = pkb2(h0, h1), hiB = pkb2(h2, h3);
        uint32_t loA = pkb2(__float2bfloat16(x.x - __bfloat162float(h0)),
                            __float2bfloat16(x.y - __bfloat162float(h1)));
        uint32_t loB = pkb2(__float2bfloat16(x.z - __bfloat162float(h2)),
                            __float2bfloat16(x.w - __bfloat162float(h3)));
        size_t b = (size_t)i4 * 4;
        uint32_t* ph = (uint32_t*)(g_ah + b);
        ph[0] = hiA; ph[1] = hiB;
        uint32_t* pl = (uint32_t*)(g_al + b);
        pl[0] = loA; pl[1] = loB;
    } else if (bid < 8192) {
        int zz = bid - 4096;
        int z  = zz >> 10;
        int zb = zz & 1023;
        int n0 = (zb & 31) * 32, k0 = (zb >> 5) * 32;
        const float* W = (z == 0) ? Wq : (z == 1) ? Wk : (z == 2) ? Wv : Wo;
        __nv_bfloat16* dh = g_wh + (size_t)z * DDIM * DDIM;
        __nv_bfloat16* dl = g_wl + (size_t)z * DDIM * DDIM;
        const int tx = tid & 31, ty0 = tid >> 5;
        #pragma unroll
        for (int r = 0; r < 4; r++) {
            int ty = ty0 + r * 8;
            tile[ty][tx] = W[(size_t)(k0 + ty) * DDIM + n0 + tx];
        }
        __syncthreads();
        #pragma unroll
        for (int r = 0; r < 4; r++) {
            int ty = ty0 + r * 8;
            float x = tile[tx][ty];
            __nv_bfloat16 h = __float2bfloat16(x);
            __nv_bfloat16 l = __float2bfloat16(x - __bfloat162float(h));
            size_t b = (size_t)(n0 + ty) * DDIM + (k0 + tx);
            dh[b] = h;
            dl[b] = l;
        }
    } else if (bid < 8450) {
        int idx = (bid - 8192) * 256 + tid;
        if (idx < HH * 4127) {
            int h   = idx / 4127;
            int r   = idx - h * 4127;
            int rel = r - BIAS_OFF;
            int ret = (rel > 0) ? 16 : 0;
            int n   = rel < 0 ? -rel : rel;
            int bkt;
            if (n < 8) {
                bkt = n;
            } else {
                float nf = (float)n;
                int vl = 8 + (int)(logf(nf * 0.125f) / 2.772588722239781f * 8.0f);
                bkt = vl < 15 ? vl : 15;
            }
            bkt += ret;
            g_bias[h * BIAS_STRIDE + r] = rel_table[bkt * HH + h];
        }
    } else {
        int idx = (bid - 8450) * 256 + tid;
        int d  = idx & 63;
        int p  = (idx >> 6) & 31;
        int bh = idx >> 11;
        size_t o = ((size_t)bh * LKV + p) * DH + d;
        float kx = pk[idx], vx = pv[idx];
        __nv_bfloat16 khf = __float2bfloat16(kx);
        __nv_bfloat16 vhf = __float2bfloat16(vx);
        g_kh[o] = khf;
        g_kl[o] = __float2bfloat16(kx - __bfloat162float(khf));
        g_vh[o] = vhf;
        g_vl[o] = __float2bfloat16(vx - __bfloat162float(vhf));
    }
}

// ---------------- mma.sync bf16 GEMM (unchanged from round 14) ----------------
#define CHUNK 64
#define NSTG 3
#define STG_BYTES 32768
#define NCH 48
#define GEMM_SMEM (NSTG * STG_BYTES)

__device__ __forceinline__ void gemm_load_chunk(uint32_t sb,
        const __nv_bfloat16* __restrict__ Ah, const __nv_bfloat16* __restrict__ Al,
        const __nv_bfloat16* __restrict__ Wh, const __nv_bfloat16* __restrict__ Wl,
        int mblock, int nblock, int c)
{
    const int t = threadIdx.x;
    const int st = c % NSTG;
    uint32_t ab = sb + st * STG_BYTES;
    uint32_t bb = ab + 16384;
    const __nv_bfloat16* Ag = (c < 32) ? Ah : Al;
    const __nv_bfloat16* Wg = (c < 16 || c >= 32) ? Wh : Wl;
    const int co = (c & 15) * CHUNK;
    #pragma unroll
    for (int i = 0; i < 4; i++) {
        int idx = t + i * 256;
        int r = idx >> 3, q = idx & 7;
        uint32_t soff = (uint32_t)(r * 128 + ((q ^ (r & 7)) << 4));
        const char* as = (const char*)(Ag + (size_t)(mblock + r) * DDIM + co + q * 8);
        const char* bs = (const char*)(Wg + (size_t)(nblock + r) * DDIM + co + q * 8);
        cpa16(ab + soff, as);
        cpa16(bb + soff, bs);
    }
    CP_COMMIT();
}

__device__ __forceinline__ void gemm_mma_body(
        const __nv_bfloat16* __restrict__ Ah, const __nv_bfloat16* __restrict__ Al,
        const __nv_bfloat16* __restrict__ Wh, const __nv_bfloat16* __restrict__ Wl,
        int mblock, int nblock, int flavor, float* __restrict__ outp)
{
    extern __shared__ __align__(128) char smbuf[];
    uint32_t sb = smem_u32(smbuf);
    const int t    = threadIdx.x;
    const int lane = t & 31;
    const int w    = t >> 5;
    const int wm   = w >> 1;
    const int wn   = w & 1;
    const int kso  = w & 3;

    float acc[2][8][4];
    #pragma unroll
    for (int f = 0; f < 2; f++)
        #pragma unroll
        for (int p = 0; p < 8; p++)
            #pragma unroll
            for (int e = 0; e < 4; e++) acc[f][p][e] = 0.f;

    gemm_load_chunk(sb, Ah, Al, Wh, Wl, mblock, nblock, 0);
    gemm_load_chunk(sb, Ah, Al, Wh, Wl, mblock, nblock, 1);

    for (int c = 0; c < NCH; c++) {
        if (c < NCH - 1) asm volatile("cp.async.wait_group 1;" ::: "memory");
        else             asm volatile("cp.async.wait_group 0;" ::: "memory");
        __syncthreads();
        if (c + 2 < NCH) gemm_load_chunk(sb, Ah, Al, Wh, Wl, mblock, nblock, c + 2);

        uint32_t ab = sb + (c % NSTG) * STG_BYTES;
        uint32_t bb = ab + 16384;

        #pragma unroll
        for (int ks2 = 0; ks2 < 4; ks2++) {
            const int ks = (ks2 + kso) & 3;
            uint32_t afr[2][4];
            #pragma unroll
            for (int f = 0; f < 2; f++) {
                int r = wm * 32 + f * 16 + (lane & 15);
                int k = ks * 16 + (lane >> 4) * 8;
                ldsm_x4(afr[f], sw_addr128(ab, r, k));
            }
            uint32_t bfr[8][2];
            #pragma unroll
            for (int p = 0; p < 4; p++) {
                int n = wn * 64 + p * 16 + ((lane >> 4) & 1) * 8 + (lane & 7);
                int k = ks * 16 + ((lane >> 3) & 1) * 8;
                uint32_t r4[4];
                ldsm_x4(r4, sw_addr128(bb, n, k));
                bfr[p * 2][0]     = r4[0];
                bfr[p * 2][1]     = r4[1];
                bfr[p * 2 + 1][0] = r4[2];
                bfr[p * 2 + 1][1] = r4[3];
            }
            #pragma unroll
            for (int f = 0; f < 2; f++)
                #pragma unroll
                for (int p = 0; p < 8; p++)
                    mma16816(acc[f][p], afr[f], bfr[p]);
        }
    }

    #pragma unroll
    for (int f = 0; f < 2; f++) {
        #pragma unroll
        for (int p = 0; p < 8; p++) {
            #pragma unroll
            for (int e2 = 0; e2 < 2; e2++) {
                int m  = mblock + wm * 32 + f * 16 + (lane >> 2) + e2 * 8;
                int n0 = nblock + wn * 64 + p * 8 + ((lane & 3) << 1);
                float v0 = acc[f][p][e2 * 2], v1 = acc[f][p][e2 * 2 + 1];
                if (flavor == 3) {
                    outp[(size_t)m * DDIM + n0]     = v0;
                    outp[(size_t)m * DDIM + n0 + 1] = v1;
                } else {
                    __nv_bfloat16 h0 = __float2bfloat16(v0), h1 = __float2bfloat16(v1);
                    uint32_t hi = pkb2(h0, h1);
                    uint32_t lo = pkb2(__float2bfloat16(v0 - __bfloat162float(h0)),
                                       __float2bfloat16(v1 - __bfloat162float(h1)));
                    int b0 = m >> 11, s = m & 2047, hh = n0 >> 6, d = n0 & 63;
                    int bh = b0 * HH + hh;
                    if (flavor == 0) {
                        size_t o = ((size_t)bh * SS + s) * DH + d;
                        *(uint32_t*)(g_qh + o) = hi;
                        *(uint32_t*)(g_ql + o) = lo;
                    } else {
                        size_t o = ((size_t)bh * LKV + PFX + s) * DH + d;
                        if (flavor == 1) {
                            *(uint32_t*)(g_kh + o) = hi;
                            *(uint32_t*)(g_kl + o) = lo;
                        } else {
                            *(uint32_t*)(g_vh + o) = hi;
                            *(uint32_t*)(g_vl + o) = lo;
                        }
                    }
                }
            }
        }
    }
}

__global__ __launch_bounds__(256, 2) void gemm_qkv_mma()
{
    const int z = blockIdx.z;
    gemm_mma_body(g_ah, g_al,
                  g_wh + (size_t)z * DDIM * DDIM, g_wl + (size_t)z * DDIM * DDIM,
                  blockIdx.y * 128, blockIdx.x * 128, z, nullptr);
}

__global__ __launch_bounds__(256, 2) void gemm_o_mma(float* __restrict__ out)
{
    gemm_mma_body(g_oh, g_ol,
                  g_wh + (size_t)3 * DDIM * DDIM, g_wl + (size_t)3 * DDIM * DDIM,
                  blockIdx.y * 128, blockIdx.x * 128, 3, out);
}

// ---------------- mma.sync flash attention ----------------
// Paired 64-key softmax; single-sync pipeline; per-warp tile-order rotation.
#define ATTN_SMEM 65536

__device__ __forceinline__ void attn_load_kv_nc(int t, int bh, int kt, uint32_t base)
{
    #pragma unroll
    for (int i = 0; i < 2; i++) {
        const int row = (t >> 3) + i * 16;
        const int c = t & 7;
        uint32_t off = (uint32_t)(row * 128 + ((c ^ (row & 7)) << 4));
        size_t goff = ((size_t)bh * LKV + kt * 32 + row) * DH + c * 8;
        cpa16(base + off,         g_kh + goff);
        cpa16(base + 4096 + off,  g_kl + goff);
        cpa16(base + 8192 + off,  g_vh + goff);
        cpa16(base + 12288 + off, g_vl + goff);
    }
}

__device__ __forceinline__ void qk32(float (*sfr)[4], uint32_t kbb,
        const uint32_t (*qh)[4], const uint32_t (*ql)[4], int lane)
{
    #pragma unroll
    for (int j = 0; j < 4; j++) {
        #pragma unroll
        for (int gk2 = 0; gk2 < 2; gk2++) {
            int row = gk2 * 16 + ((lane >> 4) << 3) + (lane & 7);
            int ch  = 2 * j + ((lane >> 3) & 1);
            uint32_t ah = kbb + row * 128 + ((ch ^ (row & 7)) << 4);
            uint32_t kh4[4], kl4[4];
            ldsm_x4(kh4, ah);
            ldsm_x4(kl4, ah + 4096);
            mma16816(sfr[2 * gk2],     qh[j], kh4);
            mma16816(sfr[2 * gk2 + 1], qh[j], kh4 + 2);
            mma16816(sfr[2 * gk2],     qh[j], kl4);
            mma16816(sfr[2 * gk2 + 1], qh[j], kl4 + 2);
            mma16816(sfr[2 * gk2],     ql[j], kh4);
            mma16816(sfr[2 * gk2 + 1], ql[j], kh4 + 2);
        }
    }
}

__device__ __forceinline__ void addbias32(float (*sfr)[4], int kb, int qrow,
        const float* __restrict__ maskb, const float* __restrict__ biash, int tc)
{
    #pragma unroll
    for (int grp = 0; grp < 4; grp++) {
        int key0 = kb + grp * 8 + tc * 2;
        float mv0 = (key0 >= PFX)     ? maskb[key0 - PFX]     : 0.f;
        float mv1 = (key0 + 1 >= PFX) ? maskb[key0 + 1 - PFX] : 0.f;
        const float* bp = biash + (key0 - qrow + (BIAS_OFF - PFX));
        sfr[grp][0] += bp[0] + mv0;
        sfr[grp][1] += bp[1] + mv1;
        sfr[grp][2] += bp[-8] + mv0;
        sfr[grp][3] += bp[-7] + mv1;
    }
}

template <int NG>
__device__ __forceinline__ void softmax_groups(float (*sfr)[4],
        float* mrow, float* lrow, float (*ofr)[4])
{
    #pragma unroll
    for (int row = 0; row < 2; row++) {
        float mx = sfr[0][row * 2];
        #pragma unroll
        for (int grp = 0; grp < NG; grp++) {
            mx = fmaxf(mx, sfr[grp][row * 2]);
            mx = fmaxf(mx, sfr[grp][row * 2 + 1]);
        }
        mx = fmaxf(mx, __shfl_xor_sync(0xffffffffu, mx, 1));
        mx = fmaxf(mx, __shfl_xor_sync(0xffffffffu, mx, 2));
        float mn = fmaxf(mrow[row], mx);
        float alpha = __expf(mrow[row] - mn);
        mrow[row] = mn;
        float sum = 0.f;
        #pragma unroll
        for (int grp = 0; grp < NG; grp++) {
            float p0 = __expf(sfr[grp][row * 2] - mn);
            float p1 = __expf(sfr[grp][row * 2 + 1] - mn);
            sfr[grp][row * 2] = p0;
            sfr[grp][row * 2 + 1] = p1;
            sum += p0 + p1;
        }
        sum += __shfl_xor_sync(0xffffffffu, sum, 1);
        sum += __shfl_xor_sync(0xffffffffu, sum, 2);
        lrow[row] = lrow[row] * alpha + sum;
        #pragma unroll
        for (int gd = 0; gd < 8; gd++) {
            ofr[gd][row * 2]     *= alpha;
            ofr[gd][row * 2 + 1] *= alpha;
        }
    }
}

__device__ __forceinline__ void pv32(float (*ofr)[4], const float (*sfr)[4],
                                     uint32_t vbb, int lane)
{
    uint32_t phi[2][4], plo[2][4];
    #pragma unroll
    for (int jk = 0; jk < 2; jk++) {
        #pragma unroll
        for (int e = 0; e < 4; e++) {
            int grp = 2 * jk + (e >> 1);
            int i0  = (e & 1) * 2;
            float p0 = sfr[grp][i0], p1 = sfr[grp][i0 + 1];
            __nv_bfloat16 h0 = __float2bfloat16(p0), h1 = __float2bfloat16(p1);
            phi[jk][e] = pkb2(h0, h1);
            plo[jk][e] = pkb2(__float2bfloat16(p0 - __bfloat162float(h0)),
                              __float2bfloat16(p1 - __bfloat162float(h1)));
        }
    }
    #pragma unroll
    for (int jk = 0; jk < 2; jk++) {
        #pragma unroll
        for (int gd2 = 0; gd2 < 4; gd2++) {
            int row = jk * 16 + (((lane >> 3) & 1) << 3) + (lane & 7);
            int ch  = 2 * gd2 + (lane >> 4);
            uint32_t av = vbb + row * 128 + ((ch ^ (row & 7)) << 4);
            uint32_t vh4[4], vl4[4];
            ldsm_x4_t(vh4, av);
            ldsm_x4_t(vl4, av + 4096);
            mma16816(ofr[2 * gd2],     phi[jk], vh4);
            mma16816(ofr[2 * gd2 + 1], phi[jk], vh4 + 2);
            mma16816(ofr[2 * gd2],     phi[jk], vl4);
            mma16816(ofr[2 * gd2 + 1], phi[jk], vl4 + 2);
            mma16816(ofr[2 * gd2],     plo[jk], vh4);
            mma16816(ofr[2 * gd2 + 1], plo[jk], vh4 + 2);
        }
    }
}

__global__ __launch_bounds__(128, 3) void attn_mma_kernel(const float* __restrict__ mask)
{
    extern __shared__ char kvsm[];
    uint32_t sb0 = smem_u32(kvsm);
    const int t = threadIdx.x, lane = t & 31, w = t >> 5;
    const int g = lane >> 2, tc = lane & 3;
    const int swap = w & 1;            // per-warp tile-order rotation
    const int h = blockIdx.y, b = blockIdx.z, bh = b * HH + h;
    const int qb = blockIdx.x * 64;
    const int m0 = qb + w * 16;

    uint32_t qh[4][4], ql[4][4];
    {
        const __nv_bfloat16* qhp = g_qh + ((size_t)bh * SS + m0) * DH;
        const __nv_bfloat16* qlp = g_ql + ((size_t)bh * SS + m0) * DH;
        #pragma unroll
        for (int j = 0; j < 4; j++)
            #pragma unroll
            for (int e = 0; e < 4; e++) {
                int r = g + (e & 1) * 8;
                int k = j * 16 + tc * 2 + (e >> 1) * 8;
                qh[j][e] = *(const uint32_t*)(qhp + (size_t)r * DH + k);
                ql[j][e] = *(const uint32_t*)(qlp + (size_t)r * DH + k);
            }
    }

    float ofr[8][4];
    #pragma unroll
    for (int i = 0; i < 8; i++)
        #pragma unroll
        for (int e = 0; e < 4; e++) ofr[i][e] = 0.f;
    float mrow[2] = {-INFINITY, -INFINITY};
    float lrow[2] = {0.f, 0.f};

    const float* maskb = mask + b * SS;
    const float* biash = g_bias + h * BIAS_STRIDE;

    // prologue: tile 0 (own group), tiles 1+2 (one group)
    attn_load_kv_nc(t, bh, 0, sb0);             CP_COMMIT();
    attn_load_kv_nc(t, bh, 1, sb0 + 16384);
    attn_load_kv_nc(t, bh, 2, sb0 + 32768);     CP_COMMIT();

    float sfr[8][4];

    // ---- solo tile 0 (prefix region) ----
    asm volatile("cp.async.wait_group 1;" ::: "memory");
    __syncthreads();
    #pragma unroll
    for (int i = 0; i < 4; i++)
        #pragma unroll
        for (int e = 0; e < 4; e++) sfr[i][e] = 0.f;
    qk32(sfr, sb0, qh, ql, lane);
    addbias32(sfr, 0, m0 + g, maskb, biash, tc);
    softmax_groups<4>(sfr, mrow, lrow, ofr);
    pv32(ofr, sfr, sb0 + 8192, lane);

    // ---- 32 pairs: tiles (2p+1, 2p+2); single sync per iter ----
    for (int p = 0; p < 32; p++) {
        const int ta = 2 * p + 1, tb = 2 * p + 2;
        const uint32_t ba = sb0 + (ta & 3) * 16384;
        const uint32_t bbb = sb0 + (tb & 3) * 16384;
        // wait: the only pending group is this pair (issued one iteration ago)
        asm volatile("cp.async.wait_group 0;" ::: "memory");
        __syncthreads();   // publishes ta/tb to all warps AND orders all prior-iter
                           // reads before the overwrite of their slots below
        if (p < 31) {
            attn_load_kv_nc(t, bh, 2 * p + 3, sb0 + ((2 * p + 3) & 3) * 16384);
            attn_load_kv_nc(t, bh, 2 * p + 4, sb0 + ((2 * p + 4) & 3) * 16384);
            CP_COMMIT();
        }

        #pragma unroll
        for (int i = 0; i < 8; i++)
            #pragma unroll
            for (int e = 0; e < 4; e++) sfr[i][e] = 0.f;
        if (swap) {
            qk32(sfr + 4, bbb, qh, ql, lane);
            qk32(sfr,     ba,  qh, ql, lane);
        } else {
            qk32(sfr,     ba,  qh, ql, lane);
            qk32(sfr + 4, bbb, qh, ql, lane);
        }
        addbias32(sfr,     ta * 32, m0 + g, maskb, biash, tc);
        addbias32(sfr + 4, tb * 32, m0 + g, maskb, biash, tc);
        softmax_groups<8>(sfr, mrow, lrow, ofr);
        if (swap) {
            pv32(ofr, sfr + 4, bbb + 8192, lane);
            pv32(ofr, sfr,     ba  + 8192, lane);
        } else {
            pv32(ofr, sfr,     ba  + 8192, lane);
            pv32(ofr, sfr + 4, bbb + 8192, lane);
        }
    }

    // ---- epilogue: normalize, split hi/lo, write g_oh / g_ol ----
    float inv0 = 1.f / lrow[0], inv1 = 1.f / lrow[1];
    #pragma unroll
    for (int gd = 0; gd < 8; gd++) {
        int d0 = gd * 8 + tc * 2;
        int k  = h * 64 + d0;
        #pragma unroll
        for (int row = 0; row < 2; row++) {
            float v0 = ofr[gd][row * 2]     * (row ? inv1 : inv0);
            float v1 = ofr[gd][row * 2 + 1] * (row ? inv1 : inv0);
            __nv_bfloat16 h0 = __float2bfloat16(v0), h1 = __float2bfloat16(v1);
            uint32_t hi = pkb2(h0, h1);
            uint32_t lo = pkb2(__float2bfloat16(v0 - __bfloat162float(h0)),
                               __float2bfloat16(v1 - __bfloat162float(h1)));
            size_t rbase = ((size_t)(b * SS + m0 + g + row * 8)) * DDIM + k;
            *(uint32_t*)(g_oh + rbase) = hi;
            *(uint32_t*)(g_ol + rbase) = lo;
        }
    }
}

// ---------------- launch ----------------
extern "C" void kernel_launch(void* const* d_in, const int* in_sizes, int n_in,
                              void* d_out, int out_size)
{
    const float* hidden = (const float*)d_in[0];
    const float* mask   = (const float*)d_in[1];
    const float* pk     = (const float*)d_in[2];
    const float* pv     = (const float*)d_in[3];
    const float* Wq     = (const float*)d_in[4];
    const float* Wk     = (const float*)d_in[5];
    const float* Wv     = (const float*)d_in[6];
    const float* Wo     = (const float*)d_in[7];
    const float* rel    = (const float*)d_in[8];
    float* out = (float*)d_out;

    cudaFuncSetAttribute(attn_mma_kernel,
                         cudaFuncAttributeMaxDynamicSharedMemorySize, ATTN_SMEM);
    cudaFuncSetAttribute(gemm_qkv_mma,
                         cudaFuncAttributeMaxDynamicSharedMemorySize, GEMM_SMEM);
    cudaFuncSetAttribute(gemm_o_mma,
                         cudaFuncAttributeMaxDynamicSharedMemorySize, GEMM_SMEM);

    prep_kernel<<<PREP_BLOCKS, 256>>>(hidden, Wq, Wk, Wv, Wo, pk, pv, rel);
    gemm_qkv_mma<<<dim3(8, 32, 3), 256, GEMM_SMEM>>>();
    attn_mma_kernel<<<dim3(SS / 64, HH, BB), 128, ATTN_SMEM>>>(mask);
    gemm_o_mma<<<dim3(8, 32), 256, GEMM_SMEM>>>(out);
}